// round 1
// baseline (speedup 1.0000x reference)
#include <cuda_runtime.h>
#include <cuda_bf16.h>
#include <math.h>
#include <stdint.h>

// Problem dims (fixed by the reference)
#define NB   4
#define LSEQ 1024
#define NHEAD 16
#define DHEAD 64
#define DMODEL 1024
#define DFFN 4096
#define MTOK (NB * LSEQ)   // 4096 tokens

// ---------------------------------------------------------------------------
// Scratch (device globals; no dynamic allocation allowed)
// ---------------------------------------------------------------------------
__device__ float g_Q [(size_t)MTOK * DMODEL];
__device__ float g_K [(size_t)MTOK * DMODEL];
__device__ float g_V [(size_t)MTOK * DMODEL];
__device__ float g_A [(size_t)MTOK * DMODEL];
__device__ float g_Y1[(size_t)MTOK * DMODEL];
__device__ float g_Y2[(size_t)MTOK * DMODEL];
__device__ float g_Hb[(size_t)MTOK * DFFN];
__device__ float g_F [(size_t)MTOK * DMODEL];
__device__ int   g_valid[NB];
__device__ float g_invscale[NB];

// ---------------------------------------------------------------------------
// valid-length + scaling from padding_mask (suffix padding, True = padded).
// Read as 4-byte words: zero <=> 0x0 for both int32(0) and float32(0.0f).
// ---------------------------------------------------------------------------
__global__ void k_valid(const unsigned* __restrict__ pm) {
    __shared__ int cnt[NB];
    if (threadIdx.x < NB) cnt[threadIdx.x] = 0;
    __syncthreads();
    for (int i = threadIdx.x; i < NB * LSEQ; i += blockDim.x) {
        if (pm[i] == 0u) atomicAdd(&cnt[i / LSEQ], 1);
    }
    __syncthreads();
    if (threadIdx.x < NB) {
        int c = cnt[threadIdx.x];
        g_valid[threadIdx.x] = c;
        g_invscale[threadIdx.x] = rsqrtf((float)c);
    }
}

// ---------------------------------------------------------------------------
// Generic NT SGEMM:  C[m,o] = sum_k A[m,k] * B[o,k]  (+bias[o]) (opt ReLU)
// 128x128 tile, BK=8, 256 threads, 8x8 per thread. gridDim.z batches A/B/C.
// Requires M%128==0, Nn%128==0, K%8==0 (true for all call sites).
// ---------------------------------------------------------------------------
struct GemmArgs {
    const float* A[3];
    const float* B[3];
    float*       C[3];
};

__global__ void __launch_bounds__(256)
gemm_nt(GemmArgs ga, int M, int Nn, int K, const float* __restrict__ bias, int relu) {
    const float* __restrict__ A = ga.A[blockIdx.z];
    const float* __restrict__ B = ga.B[blockIdx.z];
    float* __restrict__ C       = ga.C[blockIdx.z];

    __shared__ float As[8][128];
    __shared__ float Bs[8][128];

    const int tid = threadIdx.x;
    const int tx  = tid & 15;        // N direction
    const int ty  = tid >> 4;        // M direction
    const int row0 = blockIdx.y * 128;
    const int col0 = blockIdx.x * 128;

    const int lr = tid >> 1;         // loader row within tile (0..127)
    const int lk = (tid & 1) * 4;    // loader k offset (0 or 4)
    const float* Aload = A + (size_t)(row0 + lr) * K + lk;
    const float* Bload = B + (size_t)(col0 + lr) * K + lk;

    float acc[8][8];
#pragma unroll
    for (int i = 0; i < 8; i++)
#pragma unroll
        for (int j = 0; j < 8; j++) acc[i][j] = 0.f;

    for (int k0 = 0; k0 < K; k0 += 8) {
        float4 av = *(const float4*)(Aload + k0);
        float4 bv = *(const float4*)(Bload + k0);
        __syncthreads();
        As[lk + 0][lr] = av.x; As[lk + 1][lr] = av.y;
        As[lk + 2][lr] = av.z; As[lk + 3][lr] = av.w;
        Bs[lk + 0][lr] = bv.x; Bs[lk + 1][lr] = bv.y;
        Bs[lk + 2][lr] = bv.z; Bs[lk + 3][lr] = bv.w;
        __syncthreads();
#pragma unroll
        for (int k = 0; k < 8; k++) {
            float a[8], b[8];
            *(float4*)(a)     = *(const float4*)&As[k][ty * 8];
            *(float4*)(a + 4) = *(const float4*)&As[k][ty * 8 + 4];
            *(float4*)(b)     = *(const float4*)&Bs[k][tx * 8];
            *(float4*)(b + 4) = *(const float4*)&Bs[k][tx * 8 + 4];
#pragma unroll
            for (int i = 0; i < 8; i++)
#pragma unroll
                for (int j = 0; j < 8; j++)
                    acc[i][j] = fmaf(a[i], b[j], acc[i][j]);
        }
    }

    const int cb = col0 + tx * 8;
#pragma unroll
    for (int i = 0; i < 8; i++) {
        const int row = row0 + ty * 8 + i;
        float* Crow = C + (size_t)row * Nn + cb;
        if (bias) {
#pragma unroll
            for (int j = 0; j < 8; j++) acc[i][j] += bias[cb + j];
        }
        if (relu) {
#pragma unroll
            for (int j = 0; j < 8; j++) acc[i][j] = fmaxf(acc[i][j], 0.f);
        }
        float4 v0 = make_float4(acc[i][0], acc[i][1], acc[i][2], acc[i][3]);
        float4 v1 = make_float4(acc[i][4], acc[i][5], acc[i][6], acc[i][7]);
        *(float4*)(Crow)     = v0;
        *(float4*)(Crow + 4) = v1;
    }
}

// ---------------------------------------------------------------------------
// Flash attention, fp32. Q,K,V laid out (N, L, D) with head h in cols
// [h*64, h*64+64). 64-query x 64-key tiles, DH=64. Online softmax held in
// registers (per-row m, l replicated across the 16 lanes owning a row).
// Smem exactly 48 KB: Qs (d-major) + shared K/V buffer + P.
// ---------------------------------------------------------------------------
template <bool CAUSAL>
__global__ void __launch_bounds__(256)
flash_attn(const float* __restrict__ Qg, const float* __restrict__ Kg,
           const float* __restrict__ Vg, float* __restrict__ Og) {
    __shared__ float Qs[64 * 64];   // [d][q]
    __shared__ float KV[64 * 64];   // phase A: [d][k], phase B: [k][d]
    __shared__ float Ps[64 * 64];   // [q][k]

    const int n  = blockIdx.z;
    const int h  = blockIdx.y;
    const int q0 = blockIdx.x * 64;
    const int tid = threadIdx.x;
    const int tx = tid & 15;        // key / output-dim direction
    const int ty = tid >> 4;        // query direction

    const float isc = g_invscale[n];
    const int valid = g_valid[n];

    // Load Q tile transposed ([d][q]) and pre-scaled by 1/sqrt(valid).
#pragma unroll
    for (int it = 0; it < 4; it++) {
        int idx = tid + it * 256;          // 0..1023
        int qq  = idx >> 4;
        int d4  = (idx & 15) * 4;
        float4 v = *(const float4*)(Qg + ((size_t)(n * LSEQ + q0 + qq)) * DMODEL + h * DHEAD + d4);
        Qs[(d4 + 0) * 64 + qq] = v.x * isc;
        Qs[(d4 + 1) * 64 + qq] = v.y * isc;
        Qs[(d4 + 2) * 64 + qq] = v.z * isc;
        Qs[(d4 + 3) * 64 + qq] = v.w * isc;
    }

    float m_i[4], l_i[4], acc[4][4];
#pragma unroll
    for (int i = 0; i < 4; i++) {
        m_i[i] = -1e30f; l_i[i] = 0.f;
#pragma unroll
        for (int j = 0; j < 4; j++) acc[i][j] = 0.f;
    }

    const int kend = CAUSAL ? min(valid, q0 + 64) : valid;

    for (int k0 = 0; k0 < kend; k0 += 64) {
        __syncthreads();   // Q load done (iter 0) / prev PV reads done
        // Load K tile transposed ([d][k])
#pragma unroll
        for (int it = 0; it < 4; it++) {
            int idx = tid + it * 256;
            int kk  = idx >> 4;
            int d4  = (idx & 15) * 4;
            float4 v = *(const float4*)(Kg + ((size_t)(n * LSEQ + k0 + kk)) * DMODEL + h * DHEAD + d4);
            KV[(d4 + 0) * 64 + kk] = v.x;
            KV[(d4 + 1) * 64 + kk] = v.y;
            KV[(d4 + 2) * 64 + kk] = v.z;
            KV[(d4 + 3) * 64 + kk] = v.w;
        }
        __syncthreads();

        // S = Q K^T (4x4 per thread)
        float s[4][4];
#pragma unroll
        for (int i = 0; i < 4; i++)
#pragma unroll
            for (int j = 0; j < 4; j++) s[i][j] = 0.f;
#pragma unroll
        for (int d = 0; d < 64; d++) {
            float a[4], b[4];
            *(float4*)a = *(const float4*)&Qs[d * 64 + ty * 4];
            *(float4*)b = *(const float4*)&KV[d * 64 + tx * 4];
#pragma unroll
            for (int i = 0; i < 4; i++)
#pragma unroll
                for (int j = 0; j < 4; j++)
                    s[i][j] = fmaf(a[i], b[j], s[i][j]);
        }

        // Masking (causal + key padding)
#pragma unroll
        for (int i = 0; i < 4; i++) {
            const int qg = q0 + ty * 4 + i;
#pragma unroll
            for (int j = 0; j < 4; j++) {
                const int kg = k0 + tx * 4 + j;
                bool bad = (kg >= valid) || (CAUSAL && kg > qg);
                if (bad) s[i][j] = -1e30f;
            }
        }

        // Online softmax per query row (16 lanes per row; xor-shuffles stay
        // inside the 16-lane half-warp that owns the row).
#pragma unroll
        for (int i = 0; i < 4; i++) {
            float tm = fmaxf(fmaxf(s[i][0], s[i][1]), fmaxf(s[i][2], s[i][3]));
#pragma unroll
            for (int off = 8; off; off >>= 1)
                tm = fmaxf(tm, __shfl_xor_sync(0xffffffffu, tm, off));
            const float mn = fmaxf(m_i[i], tm);
            const float al = __expf(m_i[i] - mn);
            float ls = 0.f;
#pragma unroll
            for (int j = 0; j < 4; j++) {
                const float p = __expf(s[i][j] - mn);
                s[i][j] = p;
                ls += p;
            }
#pragma unroll
            for (int off = 8; off; off >>= 1)
                ls += __shfl_xor_sync(0xffffffffu, ls, off);
            l_i[i] = l_i[i] * al + ls;
            m_i[i] = mn;
#pragma unroll
            for (int j = 0; j < 4; j++) acc[i][j] *= al;
            *(float4*)&Ps[(ty * 4 + i) * 64 + tx * 4] = *(float4*)s[i];
        }
        __syncthreads();

        // Load V tile natural ([k][d]) into the same buffer
#pragma unroll
        for (int it = 0; it < 4; it++) {
            int idx = tid + it * 256;
            int kk  = idx >> 4;
            int d4  = (idx & 15) * 4;
            float4 v = *(const float4*)(Vg + ((size_t)(n * LSEQ + k0 + kk)) * DMODEL + h * DHEAD + d4);
            *(float4*)&KV[kk * 64 + d4] = v;
        }
        __syncthreads();

        // O += P V
#pragma unroll
        for (int k = 0; k < 64; k++) {
            float p[4], v[4];
#pragma unroll
            for (int i = 0; i < 4; i++) p[i] = Ps[(ty * 4 + i) * 64 + k];
            *(float4*)v = *(const float4*)&KV[k * 64 + tx * 4];
#pragma unroll
            for (int i = 0; i < 4; i++)
#pragma unroll
                for (int j = 0; j < 4; j++)
                    acc[i][j] = fmaf(p[i], v[j], acc[i][j]);
        }
    }

    // Epilogue: divide by l, store
#pragma unroll
    for (int i = 0; i < 4; i++) {
        const float inv = 1.0f / l_i[i];
        const int qg = q0 + ty * 4 + i;
        float4 ov = make_float4(acc[i][0] * inv, acc[i][1] * inv,
                                acc[i][2] * inv, acc[i][3] * inv);
        *(float4*)(Og + ((size_t)(n * LSEQ + qg)) * DMODEL + h * DHEAD + tx * 4) = ov;
    }
}

// ---------------------------------------------------------------------------
// Fused residual add + LayerNorm over last dim (1024). One block per row.
// ---------------------------------------------------------------------------
__global__ void __launch_bounds__(256)
add_ln(const float* __restrict__ a, const float* __restrict__ r,
       const float* __restrict__ g, const float* __restrict__ b,
       float* __restrict__ o) {
    const int row = blockIdx.x;
    const int t = threadIdx.x;
    const size_t base = (size_t)row * DMODEL;

    float4 x = *(const float4*)(a + base + t * 4);
    float4 y = *(const float4*)(r + base + t * 4);
    x.x += y.x; x.y += y.y; x.z += y.z; x.w += y.w;

    float s  = x.x + x.y + x.z + x.w;
    float s2 = x.x * x.x + x.y * x.y + x.z * x.z + x.w * x.w;
#pragma unroll
    for (int off = 16; off; off >>= 1) {
        s  += __shfl_xor_sync(0xffffffffu, s,  off);
        s2 += __shfl_xor_sync(0xffffffffu, s2, off);
    }
    __shared__ float sh[16];
    const int w = t >> 5, ln = t & 31;
    if (ln == 0) { sh[w] = s; sh[8 + w] = s2; }
    __syncthreads();
    s = 0.f; s2 = 0.f;
#pragma unroll
    for (int ww = 0; ww < 8; ww++) { s += sh[ww]; s2 += sh[8 + ww]; }

    const float mu  = s * (1.0f / DMODEL);
    const float var = s2 * (1.0f / DMODEL) - mu * mu;
    const float rs  = rsqrtf(var + 1e-5f);

    float4 gv = *(const float4*)(g + t * 4);
    float4 bv = *(const float4*)(b + t * 4);
    float4 ov;
    ov.x = (x.x - mu) * rs * gv.x + bv.x;
    ov.y = (x.y - mu) * rs * gv.y + bv.y;
    ov.z = (x.z - mu) * rs * gv.z + bv.z;
    ov.w = (x.w - mu) * rs * gv.w + bv.w;
    *(float4*)(o + base + t * 4) = ov;
}

// ---------------------------------------------------------------------------
// Orchestration
// ---------------------------------------------------------------------------
extern "C" void kernel_launch(void* const* d_in, const int* in_sizes, int n_in,
                              void* d_out, int out_size) {
    (void)in_sizes; (void)n_in; (void)out_size;

    const float* encoded = (const float*)d_in[0];
    const float* Yin     = (const float*)d_in[1];
    // d_in[2] = causal mask (structural; implemented directly)
    const unsigned* pmask = (const unsigned*)d_in[3];
    const float* Wq1 = (const float*)d_in[4];
    const float* Wk1 = (const float*)d_in[5];
    const float* Wv1 = (const float*)d_in[6];
    const float* g1  = (const float*)d_in[7];
    const float* b1  = (const float*)d_in[8];
    const float* Wq2 = (const float*)d_in[9];
    const float* Wk2 = (const float*)d_in[10];
    const float* Wv2 = (const float*)d_in[11];
    const float* g2  = (const float*)d_in[12];
    const float* b2  = (const float*)d_in[13];
    const float* We  = (const float*)d_in[14];
    const float* be  = (const float*)d_in[15];
    const float* Wc  = (const float*)d_in[16];
    const float* bc  = (const float*)d_in[17];
    const float* g3  = (const float*)d_in[18];
    const float* b3  = (const float*)d_in[19];
    float* out = (float*)d_out;

    float *pQ, *pK, *pV, *pA, *pY1, *pY2, *pH, *pF;
    cudaGetSymbolAddress((void**)&pQ,  g_Q);
    cudaGetSymbolAddress((void**)&pK,  g_K);
    cudaGetSymbolAddress((void**)&pV,  g_V);
    cudaGetSymbolAddress((void**)&pA,  g_A);
    cudaGetSymbolAddress((void**)&pY1, g_Y1);
    cudaGetSymbolAddress((void**)&pY2, g_Y2);
    cudaGetSymbolAddress((void**)&pH,  g_Hb);
    cudaGetSymbolAddress((void**)&pF,  g_F);

    // 0) valid lengths + scaling
    k_valid<<<1, 256>>>(pmask);

    // 1) self-attn QKV projections (one batched launch, z=3)
    {
        GemmArgs ga;
        ga.A[0] = Yin; ga.A[1] = Yin; ga.A[2] = Yin;
        ga.B[0] = Wq1; ga.B[1] = Wk1; ga.B[2] = Wv1;
        ga.C[0] = pQ;  ga.C[1] = pK;  ga.C[2] = pV;
        gemm_nt<<<dim3(DMODEL / 128, MTOK / 128, 3), 256>>>(ga, MTOK, DMODEL, DMODEL, nullptr, 0);
    }

    // 2) masked self-attention
    flash_attn<true><<<dim3(LSEQ / 64, NHEAD, NB), 256>>>(pQ, pK, pV, pA);

    // 3) residual + LN1
    add_ln<<<MTOK, 256>>>(pA, Yin, g1, b1, pY1);

    // 4) cross-attn projections: Q from Y1, K/V from encoded (one launch, z=3)
    {
        GemmArgs ga;
        ga.A[0] = pY1;     ga.A[1] = encoded; ga.A[2] = encoded;
        ga.B[0] = Wq2;     ga.B[1] = Wk2;     ga.B[2] = Wv2;
        ga.C[0] = pQ;      ga.C[1] = pK;      ga.C[2] = pV;
        gemm_nt<<<dim3(DMODEL / 128, MTOK / 128, 3), 256>>>(ga, MTOK, DMODEL, DMODEL, nullptr, 0);
    }

    // 5) cross-attention (no causal mask)
    flash_attn<false><<<dim3(LSEQ / 64, NHEAD, NB), 256>>>(pQ, pK, pV, pA);

    // 6) residual + LN2
    add_ln<<<MTOK, 256>>>(pA, pY1, g2, b2, pY2);

    // 7) FFN up: H = relu(Y2 @ We^T + be)
    {
        GemmArgs ga;
        ga.A[0] = pY2; ga.A[1] = pY2; ga.A[2] = pY2;
        ga.B[0] = We;  ga.B[1] = We;  ga.B[2] = We;
        ga.C[0] = pH;  ga.C[1] = pH;  ga.C[2] = pH;
        gemm_nt<<<dim3(DFFN / 128, MTOK / 128, 1), 256>>>(ga, MTOK, DFFN, DMODEL, be, 1);
    }

    // 8) FFN down: F = H @ Wc^T + bc
    {
        GemmArgs ga;
        ga.A[0] = pH; ga.A[1] = pH; ga.A[2] = pH;
        ga.B[0] = Wc; ga.B[1] = Wc; ga.B[2] = Wc;
        ga.C[0] = pF; ga.C[1] = pF; ga.C[2] = pF;
        gemm_nt<<<dim3(DMODEL / 128, MTOK / 128, 1), 256>>>(ga, MTOK, DMODEL, DFFN, bc, 0);
    }

    // 9) residual + LN3 -> output
    add_ln<<<MTOK, 256>>>(pF, pY2, g3, b3, out);
}

// round 3
// speedup vs baseline: 2.0948x; 2.0948x over previous
#include <cuda_runtime.h>
#include <cuda_bf16.h>
#include <math.h>
#include <stdint.h>

// Problem dims (fixed by the reference)
#define NB   4
#define LSEQ 1024
#define NHEAD 16
#define DHEAD 64
#define DMODEL 1024
#define DFFN 4096
#define MTOK (NB * LSEQ)   // 4096 tokens

// ---------------------------------------------------------------------------
// Scratch (device globals; no dynamic allocation allowed)
// ---------------------------------------------------------------------------
__device__ float g_Q [(size_t)MTOK * DMODEL];
__device__ float g_K [(size_t)MTOK * DMODEL];
__device__ float g_V [(size_t)MTOK * DMODEL];
__device__ float g_A [(size_t)MTOK * DMODEL];
__device__ float g_Y1[(size_t)MTOK * DMODEL];
__device__ float g_Y2[(size_t)MTOK * DMODEL];
__device__ float g_Hb[(size_t)MTOK * DFFN];
__device__ float g_F [(size_t)MTOK * DMODEL];
__device__ int   g_valid[NB];
__device__ float g_invscale[NB];

// ---------------------------------------------------------------------------
// Helpers
// ---------------------------------------------------------------------------
__device__ __forceinline__ uint32_t smem_u32(const void* p) {
    uint32_t a;
    asm("{ .reg .u64 t; cvta.to.shared.u64 t, %1; cvt.u32.u64 %0, t; }" : "=r"(a) : "l"(p));
    return a;
}
__device__ __forceinline__ void cp16(uint32_t dst, const void* src) {
    asm volatile("cp.async.cg.shared.global [%0], [%1], 16;" :: "r"(dst), "l"(src));
}
__device__ __forceinline__ void mma_tf32(float* d, const uint32_t* a, const uint32_t* b) {
    asm volatile(
        "mma.sync.aligned.m16n8k8.row.col.f32.tf32.tf32.f32 "
        "{%0,%1,%2,%3}, {%4,%5,%6,%7}, {%8,%9}, {%0,%1,%2,%3};"
        : "+f"(d[0]), "+f"(d[1]), "+f"(d[2]), "+f"(d[3])
        : "r"(a[0]), "r"(a[1]), "r"(a[2]), "r"(a[3]), "r"(b[0]), "r"(b[1]));
}

// ---------------------------------------------------------------------------
// valid-length + scaling from padding_mask (suffix padding, True = padded).
// ---------------------------------------------------------------------------
__global__ void k_valid(const unsigned* __restrict__ pm) {
    __shared__ int cnt[NB];
    if (threadIdx.x < NB) cnt[threadIdx.x] = 0;
    __syncthreads();
    for (int i = threadIdx.x; i < NB * LSEQ; i += blockDim.x) {
        if (pm[i] == 0u) atomicAdd(&cnt[i / LSEQ], 1);
    }
    __syncthreads();
    if (threadIdx.x < NB) {
        int c = cnt[threadIdx.x];
        g_valid[threadIdx.x] = c;
        g_invscale[threadIdx.x] = rsqrtf((float)c);
    }
}

// ---------------------------------------------------------------------------
// TF32 mma.sync NT GEMM: C[m,o] = sum_k A[m,k]*B[o,k] (+bias[o]) (opt ReLU)
// BM=128, BN=128, BK=16; 256 threads = 8 warps (4 M x 2 N); warp tile 32x64.
// Smem rows padded to 20 floats -> conflict-free fragment loads.
// ---------------------------------------------------------------------------
#define BM 128
#define BN 128
#define BK 16
#define RS 20               // smem row stride in floats (16 data + 4 pad)

struct GemmArgs {
    const float* A[3];
    const float* B[3];
    float*       C[3];
};

__global__ void __launch_bounds__(256)
gemm_tc(GemmArgs ga, int Nn, int K, const float* __restrict__ bias, int relu) {
    __shared__ float As[2][BM * RS];
    __shared__ float Bs[2][BN * RS];

    const float* __restrict__ A = ga.A[blockIdx.z];
    const float* __restrict__ B = ga.B[blockIdx.z];
    float* __restrict__ C       = ga.C[blockIdx.z];

    const int row0 = blockIdx.y * BM;
    const int col0 = blockIdx.x * BN;
    const int tid  = threadIdx.x;
    const int warp = tid >> 5;
    const int lane = tid & 31;
    const int g = lane >> 2;        // 0..7
    const int t = lane & 3;         // 0..3
    const int wm = (warp & 3) * 32; // warp M offset
    const int wn = (warp >> 2) * 64;// warp N offset

    const uint32_t sA[2] = { smem_u32(&As[0][0]), smem_u32(&As[1][0]) };
    const uint32_t sB[2] = { smem_u32(&Bs[0][0]), smem_u32(&Bs[1][0]) };

    // loader indices: 512 16B units per operand per chunk; 2 per thread
    const int lr0 = tid >> 1;              // unit tid   -> r = tid>>2... use explicit
    (void)lr0;

    float acc[2][8][4];
#pragma unroll
    for (int i = 0; i < 2; i++)
#pragma unroll
        for (int j = 0; j < 8; j++)
#pragma unroll
            for (int q = 0; q < 4; q++) acc[i][j][q] = 0.f;

    const int NC = K / BK;

    // prologue: load chunk 0 into buf 0
#pragma unroll
    for (int it = 0; it < 2; it++) {
        int u = tid + it * 256;            // 0..511
        int r = u >> 2, x = u & 3;
        cp16(sA[0] + (r * RS + x * 4) * 4, A + (size_t)(row0 + r) * K + x * 4);
        cp16(sB[0] + (r * RS + x * 4) * 4, B + (size_t)(col0 + r) * K + x * 4);
    }
    asm volatile("cp.async.commit_group;" ::: "memory");

    for (int c = 0; c < NC; ++c) {
        const int cur = c & 1;
        if (c + 1 < NC) {
            const int nb = cur ^ 1;
            const int kc = (c + 1) * BK;
#pragma unroll
            for (int it = 0; it < 2; it++) {
                int u = tid + it * 256;
                int r = u >> 2, x = u & 3;
                cp16(sA[nb] + (r * RS + x * 4) * 4, A + (size_t)(row0 + r) * K + kc + x * 4);
                cp16(sB[nb] + (r * RS + x * 4) * 4, B + (size_t)(col0 + r) * K + kc + x * 4);
            }
            asm volatile("cp.async.commit_group;" ::: "memory");
            asm volatile("cp.async.wait_group 1;" ::: "memory");
        } else {
            asm volatile("cp.async.wait_group 0;" ::: "memory");
        }
        __syncthreads();

        const float* __restrict__ as = As[cur];
        const float* __restrict__ bs = Bs[cur];
#pragma unroll
        for (int ks = 0; ks < 2; ++ks) {
            const int kb = ks * 8;
            uint32_t af[2][4], bf[8][2];
#pragma unroll
            for (int mf = 0; mf < 2; mf++) {
                const int mb = wm + mf * 16;
                af[mf][0] = __float_as_uint(as[(mb + g)     * RS + kb + t]);
                af[mf][1] = __float_as_uint(as[(mb + g + 8) * RS + kb + t]);
                af[mf][2] = __float_as_uint(as[(mb + g)     * RS + kb + t + 4]);
                af[mf][3] = __float_as_uint(as[(mb + g + 8) * RS + kb + t + 4]);
            }
#pragma unroll
            for (int nf = 0; nf < 8; nf++) {
                const int nb2 = wn + nf * 8;
                bf[nf][0] = __float_as_uint(bs[(nb2 + g) * RS + kb + t]);
                bf[nf][1] = __float_as_uint(bs[(nb2 + g) * RS + kb + t + 4]);
            }
#pragma unroll
            for (int mf = 0; mf < 2; mf++)
#pragma unroll
                for (int nf = 0; nf < 8; nf++)
                    mma_tf32(acc[mf][nf], af[mf], bf[nf]);
        }
        __syncthreads();
    }

    // epilogue: c frag (m16n8): c0 (row g, col 2t), c1 (col 2t+1),
    // c2/c3 (row g+8). bias + relu fused.
#pragma unroll
    for (int mf = 0; mf < 2; mf++) {
        const int r0 = row0 + wm + mf * 16 + g;
        const int r1 = r0 + 8;
#pragma unroll
        for (int nf = 0; nf < 8; nf++) {
            const int col = col0 + wn + nf * 8 + 2 * t;
            float c0 = acc[mf][nf][0], c1 = acc[mf][nf][1];
            float c2 = acc[mf][nf][2], c3 = acc[mf][nf][3];
            if (bias) {
                float2 bv = *(const float2*)(bias + col);
                c0 += bv.x; c1 += bv.y; c2 += bv.x; c3 += bv.y;
            }
            if (relu) {
                c0 = fmaxf(c0, 0.f); c1 = fmaxf(c1, 0.f);
                c2 = fmaxf(c2, 0.f); c3 = fmaxf(c3, 0.f);
            }
            *(float2*)(C + (size_t)r0 * Nn + col) = make_float2(c0, c1);
            *(float2*)(C + (size_t)r1 * Nn + col) = make_float2(c2, c3);
        }
    }
}

// ---------------------------------------------------------------------------
// Flash attention, fp32 (unchanged from R1 — known correct).
// ---------------------------------------------------------------------------
template <bool CAUSAL>
__global__ void __launch_bounds__(256)
flash_attn(const float* __restrict__ Qg, const float* __restrict__ Kg,
           const float* __restrict__ Vg, float* __restrict__ Og) {
    __shared__ float Qs[64 * 64];   // [d][q]
    __shared__ float KV[64 * 64];   // phase A: [d][k], phase B: [k][d]
    __shared__ float Ps[64 * 64];   // [q][k]

    const int n  = blockIdx.z;
    const int h  = blockIdx.y;
    const int q0 = blockIdx.x * 64;
    const int tid = threadIdx.x;
    const int tx = tid & 15;
    const int ty = tid >> 4;

    const float isc = g_invscale[n];
    const int valid = g_valid[n];

#pragma unroll
    for (int it = 0; it < 4; it++) {
        int idx = tid + it * 256;
        int qq  = idx >> 4;
        int d4  = (idx & 15) * 4;
        float4 v = *(const float4*)(Qg + ((size_t)(n * LSEQ + q0 + qq)) * DMODEL + h * DHEAD + d4);
        Qs[(d4 + 0) * 64 + qq] = v.x * isc;
        Qs[(d4 + 1) * 64 + qq] = v.y * isc;
        Qs[(d4 + 2) * 64 + qq] = v.z * isc;
        Qs[(d4 + 3) * 64 + qq] = v.w * isc;
    }

    float m_i[4], l_i[4], acc[4][4];
#pragma unroll
    for (int i = 0; i < 4; i++) {
        m_i[i] = -1e30f; l_i[i] = 0.f;
#pragma unroll
        for (int j = 0; j < 4; j++) acc[i][j] = 0.f;
    }

    const int kend = CAUSAL ? min(valid, q0 + 64) : valid;

    for (int k0 = 0; k0 < kend; k0 += 64) {
        __syncthreads();
#pragma unroll
        for (int it = 0; it < 4; it++) {
            int idx = tid + it * 256;
            int kk  = idx >> 4;
            int d4  = (idx & 15) * 4;
            float4 v = *(const float4*)(Kg + ((size_t)(n * LSEQ + k0 + kk)) * DMODEL + h * DHEAD + d4);
            KV[(d4 + 0) * 64 + kk] = v.x;
            KV[(d4 + 1) * 64 + kk] = v.y;
            KV[(d4 + 2) * 64 + kk] = v.z;
            KV[(d4 + 3) * 64 + kk] = v.w;
        }
        __syncthreads();

        float s[4][4];
#pragma unroll
        for (int i = 0; i < 4; i++)
#pragma unroll
            for (int j = 0; j < 4; j++) s[i][j] = 0.f;
#pragma unroll
        for (int d = 0; d < 64; d++) {
            float a[4], b[4];
            *(float4*)a = *(const float4*)&Qs[d * 64 + ty * 4];
            *(float4*)b = *(const float4*)&KV[d * 64 + tx * 4];
#pragma unroll
            for (int i = 0; i < 4; i++)
#pragma unroll
                for (int j = 0; j < 4; j++)
                    s[i][j] = fmaf(a[i], b[j], s[i][j]);
        }

#pragma unroll
        for (int i = 0; i < 4; i++) {
            const int qg = q0 + ty * 4 + i;
#pragma unroll
            for (int j = 0; j < 4; j++) {
                const int kg = k0 + tx * 4 + j;
                bool bad = (kg >= valid) || (CAUSAL && kg > qg);
                if (bad) s[i][j] = -1e30f;
            }
        }

#pragma unroll
        for (int i = 0; i < 4; i++) {
            float tm = fmaxf(fmaxf(s[i][0], s[i][1]), fmaxf(s[i][2], s[i][3]));
#pragma unroll
            for (int off = 8; off; off >>= 1)
                tm = fmaxf(tm, __shfl_xor_sync(0xffffffffu, tm, off));
            const float mn = fmaxf(m_i[i], tm);
            const float al = __expf(m_i[i] - mn);
            float ls = 0.f;
#pragma unroll
            for (int j = 0; j < 4; j++) {
                const float p = __expf(s[i][j] - mn);
                s[i][j] = p;
                ls += p;
            }
#pragma unroll
            for (int off = 8; off; off >>= 1)
                ls += __shfl_xor_sync(0xffffffffu, ls, off);
            l_i[i] = l_i[i] * al + ls;
            m_i[i] = mn;
#pragma unroll
            for (int j = 0; j < 4; j++) acc[i][j] *= al;
            *(float4*)&Ps[(ty * 4 + i) * 64 + tx * 4] = *(float4*)s[i];
        }
        __syncthreads();

#pragma unroll
        for (int it = 0; it < 4; it++) {
            int idx = tid + it * 256;
            int kk  = idx >> 4;
            int d4  = (idx & 15) * 4;
            float4 v = *(const float4*)(Vg + ((size_t)(n * LSEQ + k0 + kk)) * DMODEL + h * DHEAD + d4);
            *(float4*)&KV[kk * 64 + d4] = v;
        }
        __syncthreads();

#pragma unroll
        for (int k = 0; k < 64; k++) {
            float p[4], v[4];
#pragma unroll
            for (int i = 0; i < 4; i++) p[i] = Ps[(ty * 4 + i) * 64 + k];
            *(float4*)v = *(const float4*)&KV[k * 64 + tx * 4];
#pragma unroll
            for (int i = 0; i < 4; i++)
#pragma unroll
                for (int j = 0; j < 4; j++)
                    acc[i][j] = fmaf(p[i], v[j], acc[i][j]);
        }
    }

#pragma unroll
    for (int i = 0; i < 4; i++) {
        const float inv = 1.0f / l_i[i];
        const int qg = q0 + ty * 4 + i;
        float4 ov = make_float4(acc[i][0] * inv, acc[i][1] * inv,
                                acc[i][2] * inv, acc[i][3] * inv);
        *(float4*)(Og + ((size_t)(n * LSEQ + qg)) * DMODEL + h * DHEAD + tx * 4) = ov;
    }
}

// ---------------------------------------------------------------------------
// Fused residual add + LayerNorm over last dim (1024). One block per row.
// ---------------------------------------------------------------------------
__global__ void __launch_bounds__(256)
add_ln(const float* __restrict__ a, const float* __restrict__ r,
       const float* __restrict__ g, const float* __restrict__ b,
       float* __restrict__ o) {
    const int row = blockIdx.x;
    const int t = threadIdx.x;
    const size_t base = (size_t)row * DMODEL;

    float4 x = *(const float4*)(a + base + t * 4);
    float4 y = *(const float4*)(r + base + t * 4);
    x.x += y.x; x.y += y.y; x.z += y.z; x.w += y.w;

    float s  = x.x + x.y + x.z + x.w;
    float s2 = x.x * x.x + x.y * x.y + x.z * x.z + x.w * x.w;
#pragma unroll
    for (int off = 16; off; off >>= 1) {
        s  += __shfl_xor_sync(0xffffffffu, s,  off);
        s2 += __shfl_xor_sync(0xffffffffu, s2, off);
    }
    __shared__ float sh[16];
    const int w = t >> 5, ln = t & 31;
    if (ln == 0) { sh[w] = s; sh[8 + w] = s2; }
    __syncthreads();
    s = 0.f; s2 = 0.f;
#pragma unroll
    for (int ww = 0; ww < 8; ww++) { s += sh[ww]; s2 += sh[8 + ww]; }

    const float mu  = s * (1.0f / DMODEL);
    const float var = s2 * (1.0f / DMODEL) - mu * mu;
    const float rs  = rsqrtf(var + 1e-5f);

    float4 gv = *(const float4*)(g + t * 4);
    float4 bv = *(const float4*)(b + t * 4);
    float4 ov;
    ov.x = (x.x - mu) * rs * gv.x + bv.x;
    ov.y = (x.y - mu) * rs * gv.y + bv.y;
    ov.z = (x.z - mu) * rs * gv.z + bv.z;
    ov.w = (x.w - mu) * rs * gv.w + bv.w;
    *(float4*)(o + base + t * 4) = ov;
}

// ---------------------------------------------------------------------------
// Orchestration
// ---------------------------------------------------------------------------
extern "C" void kernel_launch(void* const* d_in, const int* in_sizes, int n_in,
                              void* d_out, int out_size) {
    (void)in_sizes; (void)n_in; (void)out_size;

    const float* encoded = (const float*)d_in[0];
    const float* Yin     = (const float*)d_in[1];
    const unsigned* pmask = (const unsigned*)d_in[3];
    const float* Wq1 = (const float*)d_in[4];
    const float* Wk1 = (const float*)d_in[5];
    const float* Wv1 = (const float*)d_in[6];
    const float* g1  = (const float*)d_in[7];
    const float* b1  = (const float*)d_in[8];
    const float* Wq2 = (const float*)d_in[9];
    const float* Wk2 = (const float*)d_in[10];
    const float* Wv2 = (const float*)d_in[11];
    const float* g2  = (const float*)d_in[12];
    const float* b2  = (const float*)d_in[13];
    const float* We  = (const float*)d_in[14];
    const float* be  = (const float*)d_in[15];
    const float* Wc  = (const float*)d_in[16];
    const float* bc  = (const float*)d_in[17];
    const float* g3  = (const float*)d_in[18];
    const float* b3  = (const float*)d_in[19];
    float* out = (float*)d_out;

    float *pQ, *pK, *pV, *pA, *pY1, *pY2, *pH, *pF;
    cudaGetSymbolAddress((void**)&pQ,  g_Q);
    cudaGetSymbolAddress((void**)&pK,  g_K);
    cudaGetSymbolAddress((void**)&pV,  g_V);
    cudaGetSymbolAddress((void**)&pA,  g_A);
    cudaGetSymbolAddress((void**)&pY1, g_Y1);
    cudaGetSymbolAddress((void**)&pY2, g_Y2);
    cudaGetSymbolAddress((void**)&pH,  g_Hb);
    cudaGetSymbolAddress((void**)&pF,  g_F);

    // 0) valid lengths + scaling
    k_valid<<<1, 256>>>(pmask);

    // 1) self-attn QKV projections (one batched launch, z=3)
    {
        GemmArgs ga;
        ga.A[0] = Yin; ga.A[1] = Yin; ga.A[2] = Yin;
        ga.B[0] = Wq1; ga.B[1] = Wk1; ga.B[2] = Wv1;
        ga.C[0] = pQ;  ga.C[1] = pK;  ga.C[2] = pV;
        gemm_tc<<<dim3(DMODEL / BN, MTOK / BM, 3), 256>>>(ga, DMODEL, DMODEL, nullptr, 0);
    }

    // 2) masked self-attention
    flash_attn<true><<<dim3(LSEQ / 64, NHEAD, NB), 256>>>(pQ, pK, pV, pA);

    // 3) residual + LN1
    add_ln<<<MTOK, 256>>>(pA, Yin, g1, b1, pY1);

    // 4) cross-attn projections: Q from Y1, K/V from encoded
    {
        GemmArgs ga;
        ga.A[0] = pY1;     ga.A[1] = encoded; ga.A[2] = encoded;
        ga.B[0] = Wq2;     ga.B[1] = Wk2;     ga.B[2] = Wv2;
        ga.C[0] = pQ;      ga.C[1] = pK;      ga.C[2] = pV;
        gemm_tc<<<dim3(DMODEL / BN, MTOK / BM, 3), 256>>>(ga, DMODEL, DMODEL, nullptr, 0);
    }

    // 5) cross-attention (no causal mask)
    flash_attn<false><<<dim3(LSEQ / 64, NHEAD, NB), 256>>>(pQ, pK, pV, pA);

    // 6) residual + LN2
    add_ln<<<MTOK, 256>>>(pA, pY1, g2, b2, pY2);

    // 7) FFN up: H = relu(Y2 @ We^T + be)
    {
        GemmArgs ga;
        ga.A[0] = pY2; ga.B[0] = We; ga.C[0] = pH;
        ga.A[1] = pY2; ga.B[1] = We; ga.C[1] = pH;
        ga.A[2] = pY2; ga.B[2] = We; ga.C[2] = pH;
        gemm_tc<<<dim3(DFFN / BN, MTOK / BM, 1), 256>>>(ga, DFFN, DMODEL, be, 1);
    }

    // 8) FFN down: F = H @ Wc^T + bc
    {
        GemmArgs ga;
        ga.A[0] = pH; ga.B[0] = Wc; ga.C[0] = pF;
        ga.A[1] = pH; ga.B[1] = Wc; ga.C[1] = pF;
        ga.A[2] = pH; ga.B[2] = Wc; ga.C[2] = pF;
        gemm_tc<<<dim3(DMODEL / BN, MTOK / BM, 1), 256>>>(ga, DMODEL, DFFN, bc, 0);
    }

    // 9) residual + LN3 -> output
    add_ln<<<MTOK, 256>>>(pF, pY2, g3, b3, out);
}

// round 4
// speedup vs baseline: 3.0215x; 1.4424x over previous
#include <cuda_runtime.h>
#include <cuda_bf16.h>
#include <math.h>
#include <stdint.h>

// Problem dims (fixed by the reference)
#define NB   4
#define LSEQ 1024
#define NHEAD 16
#define DHEAD 64
#define DMODEL 1024
#define DFFN 4096
#define MTOK (NB * LSEQ)   // 4096 tokens

// ---------------------------------------------------------------------------
// Scratch (device globals; no dynamic allocation allowed)
// ---------------------------------------------------------------------------
__device__ float g_Q [(size_t)MTOK * DMODEL];
__device__ float g_K [(size_t)MTOK * DMODEL];
__device__ float g_V [(size_t)MTOK * DMODEL];
__device__ float g_A [(size_t)MTOK * DMODEL];
__device__ float g_Y1[(size_t)MTOK * DMODEL];
__device__ float g_Y2[(size_t)MTOK * DMODEL];
__device__ float g_Hb[(size_t)MTOK * DFFN];
__device__ float g_F [(size_t)MTOK * DMODEL];
__device__ int   g_valid[NB];
__device__ float g_invscale[NB];

// ---------------------------------------------------------------------------
// Helpers
// ---------------------------------------------------------------------------
__device__ __forceinline__ uint32_t smem_u32(const void* p) {
    uint32_t a;
    asm("{ .reg .u64 t; cvta.to.shared.u64 t, %1; cvt.u32.u64 %0, t; }" : "=r"(a) : "l"(p));
    return a;
}
__device__ __forceinline__ void cp16(uint32_t dst, const void* src) {
    asm volatile("cp.async.cg.shared.global [%0], [%1], 16;" :: "r"(dst), "l"(src));
}
__device__ __forceinline__ void mma_tf32(float* d, const uint32_t* a, const uint32_t* b) {
    asm volatile(
        "mma.sync.aligned.m16n8k8.row.col.f32.tf32.tf32.f32 "
        "{%0,%1,%2,%3}, {%4,%5,%6,%7}, {%8,%9}, {%0,%1,%2,%3};"
        : "+f"(d[0]), "+f"(d[1]), "+f"(d[2]), "+f"(d[3])
        : "r"(a[0]), "r"(a[1]), "r"(a[2]), "r"(a[3]), "r"(b[0]), "r"(b[1]));
}

// ---------------------------------------------------------------------------
// valid-length + scaling from padding_mask (suffix padding, True = padded).
// ---------------------------------------------------------------------------
__global__ void k_valid(const unsigned* __restrict__ pm) {
    __shared__ int cnt[NB];
    if (threadIdx.x < NB) cnt[threadIdx.x] = 0;
    __syncthreads();
    for (int i = threadIdx.x; i < NB * LSEQ; i += blockDim.x) {
        if (pm[i] == 0u) atomicAdd(&cnt[i / LSEQ], 1);
    }
    __syncthreads();
    if (threadIdx.x < NB) {
        int c = cnt[threadIdx.x];
        g_valid[threadIdx.x] = c;
        g_invscale[threadIdx.x] = rsqrtf((float)c);
    }
}

// ---------------------------------------------------------------------------
// TF32 mma.sync NT GEMM (unchanged from R3 — passing).
// ---------------------------------------------------------------------------
#define BM 128
#define BN 128
#define BK 16
#define RS 20               // smem row stride in floats (16 data + 4 pad)

struct GemmArgs {
    const float* A[3];
    const float* B[3];
    float*       C[3];
};

__global__ void __launch_bounds__(256)
gemm_tc(GemmArgs ga, int Nn, int K, const float* __restrict__ bias, int relu) {
    __shared__ float As[2][BM * RS];
    __shared__ float Bs[2][BN * RS];

    const float* __restrict__ A = ga.A[blockIdx.z];
    const float* __restrict__ B = ga.B[blockIdx.z];
    float* __restrict__ C       = ga.C[blockIdx.z];

    const int row0 = blockIdx.y * BM;
    const int col0 = blockIdx.x * BN;
    const int tid  = threadIdx.x;
    const int warp = tid >> 5;
    const int lane = tid & 31;
    const int g = lane >> 2;
    const int t = lane & 3;
    const int wm = (warp & 3) * 32;
    const int wn = (warp >> 2) * 64;

    const uint32_t sA[2] = { smem_u32(&As[0][0]), smem_u32(&As[1][0]) };
    const uint32_t sB[2] = { smem_u32(&Bs[0][0]), smem_u32(&Bs[1][0]) };

    float acc[2][8][4];
#pragma unroll
    for (int i = 0; i < 2; i++)
#pragma unroll
        for (int j = 0; j < 8; j++)
#pragma unroll
            for (int q = 0; q < 4; q++) acc[i][j][q] = 0.f;

    const int NC = K / BK;

#pragma unroll
    for (int it = 0; it < 2; it++) {
        int u = tid + it * 256;
        int r = u >> 2, x = u & 3;
        cp16(sA[0] + (r * RS + x * 4) * 4, A + (size_t)(row0 + r) * K + x * 4);
        cp16(sB[0] + (r * RS + x * 4) * 4, B + (size_t)(col0 + r) * K + x * 4);
    }
    asm volatile("cp.async.commit_group;" ::: "memory");

    for (int c = 0; c < NC; ++c) {
        const int cur = c & 1;
        if (c + 1 < NC) {
            const int nb = cur ^ 1;
            const int kc = (c + 1) * BK;
#pragma unroll
            for (int it = 0; it < 2; it++) {
                int u = tid + it * 256;
                int r = u >> 2, x = u & 3;
                cp16(sA[nb] + (r * RS + x * 4) * 4, A + (size_t)(row0 + r) * K + kc + x * 4);
                cp16(sB[nb] + (r * RS + x * 4) * 4, B + (size_t)(col0 + r) * K + kc + x * 4);
            }
            asm volatile("cp.async.commit_group;" ::: "memory");
            asm volatile("cp.async.wait_group 1;" ::: "memory");
        } else {
            asm volatile("cp.async.wait_group 0;" ::: "memory");
        }
        __syncthreads();

        const float* __restrict__ as = As[cur];
        const float* __restrict__ bs = Bs[cur];
#pragma unroll
        for (int ks = 0; ks < 2; ++ks) {
            const int kb = ks * 8;
            uint32_t af[2][4], bf[8][2];
#pragma unroll
            for (int mf = 0; mf < 2; mf++) {
                const int mb = wm + mf * 16;
                af[mf][0] = __float_as_uint(as[(mb + g)     * RS + kb + t]);
                af[mf][1] = __float_as_uint(as[(mb + g + 8) * RS + kb + t]);
                af[mf][2] = __float_as_uint(as[(mb + g)     * RS + kb + t + 4]);
                af[mf][3] = __float_as_uint(as[(mb + g + 8) * RS + kb + t + 4]);
            }
#pragma unroll
            for (int nf = 0; nf < 8; nf++) {
                const int nb2 = wn + nf * 8;
                bf[nf][0] = __float_as_uint(bs[(nb2 + g) * RS + kb + t]);
                bf[nf][1] = __float_as_uint(bs[(nb2 + g) * RS + kb + t + 4]);
            }
#pragma unroll
            for (int mf = 0; mf < 2; mf++)
#pragma unroll
                for (int nf = 0; nf < 8; nf++)
                    mma_tf32(acc[mf][nf], af[mf], bf[nf]);
        }
        __syncthreads();
    }

#pragma unroll
    for (int mf = 0; mf < 2; mf++) {
        const int r0 = row0 + wm + mf * 16 + g;
        const int r1 = r0 + 8;
#pragma unroll
        for (int nf = 0; nf < 8; nf++) {
            const int col = col0 + wn + nf * 8 + 2 * t;
            float c0 = acc[mf][nf][0], c1 = acc[mf][nf][1];
            float c2 = acc[mf][nf][2], c3 = acc[mf][nf][3];
            if (bias) {
                float2 bv = *(const float2*)(bias + col);
                c0 += bv.x; c1 += bv.y; c2 += bv.x; c3 += bv.y;
            }
            if (relu) {
                c0 = fmaxf(c0, 0.f); c1 = fmaxf(c1, 0.f);
                c2 = fmaxf(c2, 0.f); c3 = fmaxf(c3, 0.f);
            }
            *(float2*)(C + (size_t)r0 * Nn + col) = make_float2(c0, c1);
            *(float2*)(C + (size_t)r1 * Nn + col) = make_float2(c2, c3);
        }
    }
}

// ---------------------------------------------------------------------------
// Tensor-core flash attention (tf32 mma for S=QK^T and O=PV).
// 64q x 64k tiles, 128 threads = 4 warps x 16 query rows.
// Q,K natural [row][d] stride 68 (A/B frag LDS conflict-free: bank 4g+t).
// V natural [key][d] stride 72 (B frag: bank 8t+g). K/V share one buffer.
// P stays in registers: S C-frag -> A-frag via quad shuffles.
// ---------------------------------------------------------------------------
#define QLD 68
#define VLD 72

template <bool CAUSAL>
__global__ void __launch_bounds__(128)
flash_tc(const float* __restrict__ Qg, const float* __restrict__ Kg,
         const float* __restrict__ Vg, float* __restrict__ Og) {
    __shared__ float Qs[64 * QLD];
    __shared__ float KV[64 * VLD];

    const int n  = blockIdx.z;
    const int h  = blockIdx.y;
    const int q0 = blockIdx.x * 64;
    const int tid = threadIdx.x;
    const int warp = tid >> 5;
    const int lane = tid & 31;
    const int g = lane >> 2;       // 0..7
    const int t = lane & 3;        // 0..3
    const int wm = warp * 16;      // warp's query-row offset

    const float isc = g_invscale[n];
    const int valid = g_valid[n];
    const uint32_t kvb = smem_u32(&KV[0]);

    // Load Q tile (natural [q][d], pre-scaled).
#pragma unroll
    for (int it = 0; it < 8; it++) {
        int idx = tid + it * 128;
        int qq = idx >> 4, d4 = (idx & 15) * 4;
        float4 v = *(const float4*)(Qg + ((size_t)(n * LSEQ + q0 + qq)) * DMODEL + h * DHEAD + d4);
        v.x *= isc; v.y *= isc; v.z *= isc; v.w *= isc;
        *(float4*)&Qs[qq * QLD + d4] = v;
    }

    float m_i[2] = { -1e30f, -1e30f };
    float l_i[2] = { 0.f, 0.f };
    float of[8][4];
#pragma unroll
    for (int nf = 0; nf < 8; nf++)
#pragma unroll
        for (int r = 0; r < 4; r++) of[nf][r] = 0.f;

    const int kend = CAUSAL ? min(valid, q0 + 64) : valid;

    for (int k0 = 0; k0 < kend; k0 += 64) {
        __syncthreads();   // Q stores (iter 0) / prior PV reads complete
        // K tile -> KV natural [k][d], stride QLD
#pragma unroll
        for (int it = 0; it < 8; it++) {
            int idx = tid + it * 128;
            int kk = idx >> 4, d4 = (idx & 15) * 4;
            cp16(kvb + (kk * QLD + d4) * 4,
                 Kg + ((size_t)(n * LSEQ + k0 + kk)) * DMODEL + h * DHEAD + d4);
        }
        asm volatile("cp.async.commit_group;" ::: "memory");
        asm volatile("cp.async.wait_group 0;" ::: "memory");
        __syncthreads();

        // S = Q K^T : per warp m16 x n64 x k64
        float sf[8][4];
#pragma unroll
        for (int nf = 0; nf < 8; nf++)
#pragma unroll
            for (int r = 0; r < 4; r++) sf[nf][r] = 0.f;
#pragma unroll
        for (int kb = 0; kb < 64; kb += 8) {
            uint32_t a[4];
            a[0] = __float_as_uint(Qs[(wm + g)     * QLD + kb + t]);
            a[1] = __float_as_uint(Qs[(wm + g + 8) * QLD + kb + t]);
            a[2] = __float_as_uint(Qs[(wm + g)     * QLD + kb + t + 4]);
            a[3] = __float_as_uint(Qs[(wm + g + 8) * QLD + kb + t + 4]);
#pragma unroll
            for (int nf = 0; nf < 8; nf++) {
                uint32_t b[2] = {
                    __float_as_uint(KV[(nf * 8 + g) * QLD + kb + t]),
                    __float_as_uint(KV[(nf * 8 + g) * QLD + kb + t + 4])
                };
                mma_tf32(sf[nf], a, b);
            }
        }

        __syncthreads();   // all warps done reading K from KV
        // V tile -> KV natural [k][d], stride VLD (overlaps softmax below)
#pragma unroll
        for (int it = 0; it < 8; it++) {
            int idx = tid + it * 128;
            int kk = idx >> 4, d4 = (idx & 15) * 4;
            cp16(kvb + (kk * VLD + d4) * 4,
                 Vg + ((size_t)(n * LSEQ + k0 + kk)) * DMODEL + h * DHEAD + d4);
        }
        asm volatile("cp.async.commit_group;" ::: "memory");

        // Masking (only boundary tiles)
        const bool mpad = (k0 + 64 > valid);
        const bool mcau = CAUSAL && (k0 == q0);
        if (mpad || mcau) {
#pragma unroll
            for (int nf = 0; nf < 8; nf++)
#pragma unroll
                for (int r = 0; r < 4; r++) {
                    int kg = k0 + nf * 8 + 2 * t + (r & 1);
                    int qg = q0 + wm + g + ((r >> 1) ? 8 : 0);
                    if ((mpad && kg >= valid) || (mcau && kg > qg))
                        sf[nf][r] = -1e30f;
                }
        }

        // Online softmax: each thread owns rows g (regs 0,1) and g+8 (regs 2,3)
#pragma unroll
        for (int r = 0; r < 2; r++) {
            const int j0 = 2 * r, j1 = 2 * r + 1;
            float mx = -1e30f;
#pragma unroll
            for (int nf = 0; nf < 8; nf++)
                mx = fmaxf(mx, fmaxf(sf[nf][j0], sf[nf][j1]));
            mx = fmaxf(mx, __shfl_xor_sync(0xffffffffu, mx, 1));
            mx = fmaxf(mx, __shfl_xor_sync(0xffffffffu, mx, 2));
            const float mn = fmaxf(m_i[r], mx);
            const float al = __expf(m_i[r] - mn);
            float sum = 0.f;
#pragma unroll
            for (int nf = 0; nf < 8; nf++) {
                float p0 = __expf(sf[nf][j0] - mn);
                float p1 = __expf(sf[nf][j1] - mn);
                sf[nf][j0] = p0; sf[nf][j1] = p1;
                sum += p0 + p1;
            }
            sum += __shfl_xor_sync(0xffffffffu, sum, 1);
            sum += __shfl_xor_sync(0xffffffffu, sum, 2);
            l_i[r] = l_i[r] * al + sum;
            m_i[r] = mn;
#pragma unroll
            for (int nf = 0; nf < 8; nf++) {
                of[nf][j0] *= al;
                of[nf][j1] *= al;
            }
        }

        asm volatile("cp.async.wait_group 0;" ::: "memory");
        __syncthreads();

        // O += P V : P C-frag -> A-frag via quad shuffles; V B-frag from smem
        const int s1 = 4 * g + (t >> 1);
        const int s2 = s1 + 2;
        const bool odd = (t & 1);
#pragma unroll
        for (int kt = 0; kt < 8; kt++) {
            float v0 = __shfl_sync(0xffffffffu, sf[kt][0], s1);
            float v1 = __shfl_sync(0xffffffffu, sf[kt][1], s1);
            float v2 = __shfl_sync(0xffffffffu, sf[kt][2], s1);
            float v3 = __shfl_sync(0xffffffffu, sf[kt][3], s1);
            float w0 = __shfl_sync(0xffffffffu, sf[kt][0], s2);
            float w1 = __shfl_sync(0xffffffffu, sf[kt][1], s2);
            float w2 = __shfl_sync(0xffffffffu, sf[kt][2], s2);
            float w3 = __shfl_sync(0xffffffffu, sf[kt][3], s2);
            uint32_t a[4];
            a[0] = __float_as_uint(odd ? v1 : v0);
            a[1] = __float_as_uint(odd ? v3 : v2);
            a[2] = __float_as_uint(odd ? w1 : w0);
            a[3] = __float_as_uint(odd ? w3 : w2);
#pragma unroll
            for (int nf = 0; nf < 8; nf++) {
                uint32_t b[2] = {
                    __float_as_uint(KV[(kt * 8 + t)     * VLD + nf * 8 + g]),
                    __float_as_uint(KV[(kt * 8 + t + 4) * VLD + nf * 8 + g])
                };
                mma_tf32(of[nf], a, b);
            }
        }
    }

    // Epilogue
    const float inv0 = 1.0f / l_i[0];
    const float inv1 = 1.0f / l_i[1];
    const int r0 = q0 + wm + g;
    const int r1 = r0 + 8;
#pragma unroll
    for (int nf = 0; nf < 8; nf++) {
        const int col = h * DHEAD + nf * 8 + 2 * t;
        *(float2*)(Og + ((size_t)(n * LSEQ + r0)) * DMODEL + col) =
            make_float2(of[nf][0] * inv0, of[nf][1] * inv0);
        *(float2*)(Og + ((size_t)(n * LSEQ + r1)) * DMODEL + col) =
            make_float2(of[nf][2] * inv1, of[nf][3] * inv1);
    }
}

// ---------------------------------------------------------------------------
// Fused residual add + LayerNorm over last dim (1024). One block per row.
// ---------------------------------------------------------------------------
__global__ void __launch_bounds__(256)
add_ln(const float* __restrict__ a, const float* __restrict__ r,
       const float* __restrict__ g, const float* __restrict__ b,
       float* __restrict__ o) {
    const int row = blockIdx.x;
    const int t = threadIdx.x;
    const size_t base = (size_t)row * DMODEL;

    float4 x = *(const float4*)(a + base + t * 4);
    float4 y = *(const float4*)(r + base + t * 4);
    x.x += y.x; x.y += y.y; x.z += y.z; x.w += y.w;

    float s  = x.x + x.y + x.z + x.w;
    float s2 = x.x * x.x + x.y * x.y + x.z * x.z + x.w * x.w;
#pragma unroll
    for (int off = 16; off; off >>= 1) {
        s  += __shfl_xor_sync(0xffffffffu, s,  off);
        s2 += __shfl_xor_sync(0xffffffffu, s2, off);
    }
    __shared__ float sh[16];
    const int w = t >> 5, ln = t & 31;
    if (ln == 0) { sh[w] = s; sh[8 + w] = s2; }
    __syncthreads();
    s = 0.f; s2 = 0.f;
#pragma unroll
    for (int ww = 0; ww < 8; ww++) { s += sh[ww]; s2 += sh[8 + ww]; }

    const float mu  = s * (1.0f / DMODEL);
    const float var = s2 * (1.0f / DMODEL) - mu * mu;
    const float rs  = rsqrtf(var + 1e-5f);

    float4 gv = *(const float4*)(g + t * 4);
    float4 bv = *(const float4*)(b + t * 4);
    float4 ov;
    ov.x = (x.x - mu) * rs * gv.x + bv.x;
    ov.y = (x.y - mu) * rs * gv.y + bv.y;
    ov.z = (x.z - mu) * rs * gv.z + bv.z;
    ov.w = (x.w - mu) * rs * gv.w + bv.w;
    *(float4*)(o + base + t * 4) = ov;
}

// ---------------------------------------------------------------------------
// Orchestration
// ---------------------------------------------------------------------------
extern "C" void kernel_launch(void* const* d_in, const int* in_sizes, int n_in,
                              void* d_out, int out_size) {
    (void)in_sizes; (void)n_in; (void)out_size;

    const float* encoded = (const float*)d_in[0];
    const float* Yin     = (const float*)d_in[1];
    const unsigned* pmask = (const unsigned*)d_in[3];
    const float* Wq1 = (const float*)d_in[4];
    const float* Wk1 = (const float*)d_in[5];
    const float* Wv1 = (const float*)d_in[6];
    const float* g1  = (const float*)d_in[7];
    const float* b1  = (const float*)d_in[8];
    const float* Wq2 = (const float*)d_in[9];
    const float* Wk2 = (const float*)d_in[10];
    const float* Wv2 = (const float*)d_in[11];
    const float* g2  = (const float*)d_in[12];
    const float* b2  = (const float*)d_in[13];
    const float* We  = (const float*)d_in[14];
    const float* be  = (const float*)d_in[15];
    const float* Wc  = (const float*)d_in[16];
    const float* bc  = (const float*)d_in[17];
    const float* g3  = (const float*)d_in[18];
    const float* b3  = (const float*)d_in[19];
    float* out = (float*)d_out;

    float *pQ, *pK, *pV, *pA, *pY1, *pY2, *pH, *pF;
    cudaGetSymbolAddress((void**)&pQ,  g_Q);
    cudaGetSymbolAddress((void**)&pK,  g_K);
    cudaGetSymbolAddress((void**)&pV,  g_V);
    cudaGetSymbolAddress((void**)&pA,  g_A);
    cudaGetSymbolAddress((void**)&pY1, g_Y1);
    cudaGetSymbolAddress((void**)&pY2, g_Y2);
    cudaGetSymbolAddress((void**)&pH,  g_Hb);
    cudaGetSymbolAddress((void**)&pF,  g_F);

    // 0) valid lengths + scaling
    k_valid<<<1, 256>>>(pmask);

    // 1) self-attn QKV projections
    {
        GemmArgs ga;
        ga.A[0] = Yin; ga.A[1] = Yin; ga.A[2] = Yin;
        ga.B[0] = Wq1; ga.B[1] = Wk1; ga.B[2] = Wv1;
        ga.C[0] = pQ;  ga.C[1] = pK;  ga.C[2] = pV;
        gemm_tc<<<dim3(DMODEL / BN, MTOK / BM, 3), 256>>>(ga, DMODEL, DMODEL, nullptr, 0);
    }

    // 2) masked self-attention
    flash_tc<true><<<dim3(LSEQ / 64, NHEAD, NB), 128>>>(pQ, pK, pV, pA);

    // 3) residual + LN1
    add_ln<<<MTOK, 256>>>(pA, Yin, g1, b1, pY1);

    // 4) cross-attn projections: Q from Y1, K/V from encoded
    {
        GemmArgs ga;
        ga.A[0] = pY1;     ga.A[1] = encoded; ga.A[2] = encoded;
        ga.B[0] = Wq2;     ga.B[1] = Wk2;     ga.B[2] = Wv2;
        ga.C[0] = pQ;      ga.C[1] = pK;      ga.C[2] = pV;
        gemm_tc<<<dim3(DMODEL / BN, MTOK / BM, 3), 256>>>(ga, DMODEL, DMODEL, nullptr, 0);
    }

    // 5) cross-attention (no causal mask)
    flash_tc<false><<<dim3(LSEQ / 64, NHEAD, NB), 128>>>(pQ, pK, pV, pA);

    // 6) residual + LN2
    add_ln<<<MTOK, 256>>>(pA, pY1, g2, b2, pY2);

    // 7) FFN up: H = relu(Y2 @ We^T + be)
    {
        GemmArgs ga;
        ga.A[0] = pY2; ga.B[0] = We; ga.C[0] = pH;
        ga.A[1] = pY2; ga.B[1] = We; ga.C[1] = pH;
        ga.A[2] = pY2; ga.B[2] = We; ga.C[2] = pH;
        gemm_tc<<<dim3(DFFN / BN, MTOK / BM, 1), 256>>>(ga, DFFN, DMODEL, be, 1);
    }

    // 8) FFN down: F = H @ Wc^T + bc
    {
        GemmArgs ga;
        ga.A[0] = pH; ga.B[0] = Wc; ga.C[0] = pF;
        ga.A[1] = pH; ga.B[1] = Wc; ga.C[1] = pF;
        ga.A[2] = pH; ga.B[2] = Wc; ga.C[2] = pF;
        gemm_tc<<<dim3(DMODEL / BN, MTOK / BM, 1), 256>>>(ga, DMODEL, DFFN, bc, 0);
    }

    // 9) residual + LN3 -> output
    add_ln<<<MTOK, 256>>>(pF, pY2, g3, b3, out);
}